// round 9
// baseline (speedup 1.0000x reference)
#include <cuda_runtime.h>
#include <cstdint>
#include <math.h>

#define S_LEN 2048
#define B_SZ  32
#define D_SZ  512
#define KCONV 147
#define PADC  73
#define NS    32                 // s-splits
#define ROWS_PB 64               // rows per block
#define ROWS_PW 8                // rows per warp
#define KSPL  4                  // gemm k-splits

// ---------------- scratch ----------------
__device__ float g_attp[KSPL][B_SZ * D_SZ];  // GEMM k-split partials
__device__ float g_c  [B_SZ * S_LEN];        // adj * exp(w)
__device__ float g_pz [B_SZ * NS];           // per-split sum of c
__device__ float g_pacc[B_SZ * NS * D_SZ];   // per-split weighted sums
__device__ int   g_done[B_SZ];               // per-batch arrival counters

// ---------------- kernel 1: attended = state @ W^T (k-split x4) ----------
__global__ __launch_bounds__(256) void k_gemm(const float* __restrict__ state,
                                              const float* __restrict__ W) {
    __shared__ float st[128][33];
    __shared__ float ws[8][128];
    const int tid  = threadIdx.x;
    const int lane = tid & 31;      // batch
    const int wid  = tid >> 5;      // one of 8 d's
    const int gx   = blockIdx.x, gy = blockIdx.y;
    const int k0   = gy * 128;
    const int d    = gx * 8 + wid;

    if (gx == 0 && gy == 0 && tid < B_SZ) g_done[tid] = 0;

    for (int i = tid; i < 32 * 128; i += 256) {
        int b = i >> 7, kk = i & 127;
        st[kk][b] = state[b * D_SZ + k0 + kk];
    }
    for (int i = tid; i < 8 * 128; i += 256) {
        int dd = i >> 7, kk = i & 127;
        ws[dd][kk] = W[(gx * 8 + dd) * D_SZ + k0 + kk];
    }
    __syncthreads();

    float a0 = 0.f, a1 = 0.f, a2 = 0.f, a3 = 0.f;
#pragma unroll 8
    for (int kk = 0; kk < 128; kk += 4) {
        a0 = fmaf(st[kk + 0][lane], ws[wid][kk + 0], a0);
        a1 = fmaf(st[kk + 1][lane], ws[wid][kk + 1], a1);
        a2 = fmaf(st[kk + 2][lane], ws[wid][kk + 2], a2);
        a3 = fmaf(st[kk + 3][lane], ws[wid][kk + 3], a3);
    }
    g_attp[gy][lane * D_SZ + d] = (a0 + a1) + (a2 + a3);
}

// ---------------- kernel 2: two-phase main pass (no per-row reductions) ----
// grid (B_SZ, NS); 256 threads = 8 warps; 4 blocks/SM.
__global__ __launch_bounds__(256, 4) void k_main(const float* __restrict__ enc,
                                                 const float* __restrict__ b_att,
                                                 const float* __restrict__ prev,
                                                 const float* __restrict__ cw,
                                                 const float* __restrict__ cb,
                                                 float* __restrict__ out) {
    // s_part[0] = per-lane dot partials, s_part[1] = sumsq partials.
    // Reused after phase 1.5 as the float4 combine buffer (needs 16 KB <= 18 KB).
    __shared__ __align__(16) float s_part[2][ROWS_PB][36];
    __shared__ float4 s_ns[128];                 // normalized attended state
    __shared__ float  s_spc[ROWS_PB + 2 * PADC];
    __shared__ float  s_cw[KCONV];
    __shared__ float  s_c[ROWS_PB];
    __shared__ float  s_invZ;
    __shared__ int    s_last;

    const int b   = blockIdx.x;
    const int sp  = blockIdx.y;
    const int tid = threadIdx.x, lane = tid & 31, w = tid >> 5;
    const int s0  = sp * ROWS_PB;
    const int sbase = s0 + w * ROWS_PW;
    const float4* enc4 = reinterpret_cast<const float4*>(enc);

    // ---- stage conv inputs ----
    if (tid < KCONV) s_cw[tid] = cw[tid];
    for (int i = tid; i < ROWS_PB + 2 * PADC; i += 256) {
        int s = s0 + i - PADC;
        s_spc[i] = (s >= 0 && s < S_LEN) ? prev[b * S_LEN + s] : 0.f;
    }

    // ---- warp 0: normalized attended state into s_ns ----
    if (w == 0) {
        const float4* ba4 = reinterpret_cast<const float4*>(b_att);
        float4 a0, a1, a2, a3, t;
#define LD_AT(q, dst) \
        dst = ba4[(q) * 32 + lane]; \
        _Pragma("unroll") \
        for (int p_ = 0; p_ < KSPL; p_++) { \
            t = reinterpret_cast<const float4*>(g_attp[p_])[b * 128 + (q) * 32 + lane]; \
            dst.x += t.x; dst.y += t.y; dst.z += t.z; dst.w += t.w; \
        }
        LD_AT(0, a0) LD_AT(1, a1) LD_AT(2, a2) LD_AT(3, a3)
#undef LD_AT
        float ss = a0.x*a0.x + a0.y*a0.y + a0.z*a0.z + a0.w*a0.w
                 + a1.x*a1.x + a1.y*a1.y + a1.z*a1.z + a1.w*a1.w
                 + a2.x*a2.x + a2.y*a2.y + a2.z*a2.z + a2.w*a2.w
                 + a3.x*a3.x + a3.y*a3.y + a3.z*a3.z + a3.w*a3.w;
#pragma unroll
        for (int o = 16; o; o >>= 1) ss += __shfl_xor_sync(0xffffffffu, ss, o);
        float inv = (ss > 0.f) ? rsqrtf(ss) : 1e10f;
        a0.x*=inv; a0.y*=inv; a0.z*=inv; a0.w*=inv;
        a1.x*=inv; a1.y*=inv; a1.z*=inv; a1.w*=inv;
        a2.x*=inv; a2.y*=inv; a2.z*=inv; a2.w*=inv;
        a3.x*=inv; a3.y*=inv; a3.z*=inv; a3.w*=inv;
        s_ns[0*32 + lane] = a0;
        s_ns[1*32 + lane] = a1;
        s_ns[2*32 + lane] = a2;
        s_ns[3*32 + lane] = a3;
    }
    __syncthreads();

    // ---- conv (quad per output row; thread keeps its row's adj) ----
    float adj;
    {
        const int o_ = tid >> 2, q = tid & 3;
        const int j0 = q * 37, cnt = (q < 3) ? 37 : 36;
        float a = 0.f, a2 = 0.f;
        for (int j = 0; j < cnt - 1; j += 2) {
            a  = fmaf(s_spc[o_ + j0 + j],     s_cw[j0 + j],     a);
            a2 = fmaf(s_spc[o_ + j0 + j + 1], s_cw[j0 + j + 1], a2);
        }
        if (cnt & 1) a = fmaf(s_spc[o_ + j0 + cnt - 1], s_cw[j0 + cnt - 1], a);
        float vfull = a + a2;
        vfull += __shfl_xor_sync(0xffffffffu, vfull, 1);
        vfull += __shfl_xor_sync(0xffffffffu, vfull, 2);
        adj = fmaxf(vfull + __ldg(cb), 0.f);
    }

    // ---- phase 1: stream rows, per-lane partials only (no reductions) ----
#pragma unroll
    for (int r = 0; r < ROWS_PW; r += 2) {
        const float4* gA = enc4 + ((size_t)(sbase + r)     * B_SZ + b) * 128;
        const float4* gB = enc4 + ((size_t)(sbase + r + 1) * B_SZ + b) * 128;
        float4 eA0 = gA[lane], eA1 = gA[32+lane], eA2 = gA[64+lane], eA3 = gA[96+lane];
        float4 eB0 = gB[lane], eB1 = gB[32+lane], eB2 = gB[64+lane], eB3 = gB[96+lane];

        float4 n = s_ns[lane];
        float dA = eA0.x*n.x + eA0.y*n.y + eA0.z*n.z + eA0.w*n.w;
        float sA = eA0.x*eA0.x + eA0.y*eA0.y + eA0.z*eA0.z + eA0.w*eA0.w;
        float dB = eB0.x*n.x + eB0.y*n.y + eB0.z*n.z + eB0.w*n.w;
        float sB = eB0.x*eB0.x + eB0.y*eB0.y + eB0.z*eB0.z + eB0.w*eB0.w;
        n = s_ns[32 + lane];
        dA += eA1.x*n.x + eA1.y*n.y + eA1.z*n.z + eA1.w*n.w;
        sA += eA1.x*eA1.x + eA1.y*eA1.y + eA1.z*eA1.z + eA1.w*eA1.w;
        dB += eB1.x*n.x + eB1.y*n.y + eB1.z*n.z + eB1.w*n.w;
        sB += eB1.x*eB1.x + eB1.y*eB1.y + eB1.z*eB1.z + eB1.w*eB1.w;
        n = s_ns[64 + lane];
        dA += eA2.x*n.x + eA2.y*n.y + eA2.z*n.z + eA2.w*n.w;
        sA += eA2.x*eA2.x + eA2.y*eA2.y + eA2.z*eA2.z + eA2.w*eA2.w;
        dB += eB2.x*n.x + eB2.y*n.y + eB2.z*n.z + eB2.w*n.w;
        sB += eB2.x*eB2.x + eB2.y*eB2.y + eB2.z*eB2.z + eB2.w*eB2.w;
        n = s_ns[96 + lane];
        dA += eA3.x*n.x + eA3.y*n.y + eA3.z*n.z + eA3.w*n.w;
        sA += eA3.x*eA3.x + eA3.y*eA3.y + eA3.z*eA3.z + eA3.w*eA3.w;
        dB += eB3.x*n.x + eB3.y*n.y + eB3.z*n.z + eB3.w*n.w;
        sB += eB3.x*eB3.x + eB3.y*eB3.y + eB3.z*eB3.z + eB3.w*eB3.w;

        const int row = w * ROWS_PW + r;
        s_part[0][row][lane]     = dA;
        s_part[1][row][lane]     = sA;
        s_part[0][row + 1][lane] = dB;
        s_part[1][row + 1][lane] = sB;
    }
    __syncthreads();

    // ---- phase 1.5: quad-reduce partials, compute c per row ----
    {
        const int row = tid >> 2, q = tid & 3;
        const float* pd = &s_part[0][row][q * 8];
        const float* ps = &s_part[1][row][q * 8];
        float4 v0 = *reinterpret_cast<const float4*>(pd);
        float4 v1 = *reinterpret_cast<const float4*>(pd + 4);
        float4 u0 = *reinterpret_cast<const float4*>(ps);
        float4 u1 = *reinterpret_cast<const float4*>(ps + 4);
        float dot = (v0.x + v0.y) + (v0.z + v0.w) + (v1.x + v1.y) + (v1.z + v1.w);
        float ss  = (u0.x + u0.y) + (u0.z + u0.w) + (u1.x + u1.y) + (u1.z + u1.w);
        dot += __shfl_xor_sync(0xffffffffu, dot, 1);
        dot += __shfl_xor_sync(0xffffffffu, dot, 2);
        ss  += __shfl_xor_sync(0xffffffffu, ss, 1);
        ss  += __shfl_xor_sync(0xffffffffu, ss, 2);
        if (q == 0) {
            float wt = dot * ((ss > 0.f) ? rsqrtf(ss) : 1e10f);   // |wt| <= 1
            float c = adj * __expf(wt);
            s_c[row] = c;
            g_c[b * S_LEN + s0 + row] = c;
        }
    }
    __syncthreads();

    // ---- warp 0: block csum -> g_pz ----
    if (tid < 32) {
        float z = s_c[tid] + s_c[tid + 32];
#pragma unroll
        for (int o = 16; o; o >>= 1) z += __shfl_xor_sync(0xffffffffu, z, o);
        if (tid == 0) g_pz[b * NS + sp] = z;
    }

    // ---- phase 2: re-stream rows (L2-hot), pure weighted accumulation ----
    float4 acc0 = make_float4(0,0,0,0), acc1 = acc0, acc2 = acc0, acc3 = acc0;
#pragma unroll
    for (int r = 0; r < ROWS_PW; r += 2) {
        const float4* gA = enc4 + ((size_t)(sbase + r)     * B_SZ + b) * 128;
        const float4* gB = enc4 + ((size_t)(sbase + r + 1) * B_SZ + b) * 128;
        float4 eA0 = gA[lane], eA1 = gA[32+lane], eA2 = gA[64+lane], eA3 = gA[96+lane];
        float4 eB0 = gB[lane], eB1 = gB[32+lane], eB2 = gB[64+lane], eB3 = gB[96+lane];
        float cA = s_c[w * ROWS_PW + r];
        float cB = s_c[w * ROWS_PW + r + 1];
        acc0.x = fmaf(cA, eA0.x, fmaf(cB, eB0.x, acc0.x));
        acc0.y = fmaf(cA, eA0.y, fmaf(cB, eB0.y, acc0.y));
        acc0.z = fmaf(cA, eA0.z, fmaf(cB, eB0.z, acc0.z));
        acc0.w = fmaf(cA, eA0.w, fmaf(cB, eB0.w, acc0.w));
        acc1.x = fmaf(cA, eA1.x, fmaf(cB, eB1.x, acc1.x));
        acc1.y = fmaf(cA, eA1.y, fmaf(cB, eB1.y, acc1.y));
        acc1.z = fmaf(cA, eA1.z, fmaf(cB, eB1.z, acc1.z));
        acc1.w = fmaf(cA, eA1.w, fmaf(cB, eB1.w, acc1.w));
        acc2.x = fmaf(cA, eA2.x, fmaf(cB, eB2.x, acc2.x));
        acc2.y = fmaf(cA, eA2.y, fmaf(cB, eB2.y, acc2.y));
        acc2.z = fmaf(cA, eA2.z, fmaf(cB, eB2.z, acc2.z));
        acc2.w = fmaf(cA, eA2.w, fmaf(cB, eB2.w, acc2.w));
        acc3.x = fmaf(cA, eA3.x, fmaf(cB, eB3.x, acc3.x));
        acc3.y = fmaf(cA, eA3.y, fmaf(cB, eB3.y, acc3.y));
        acc3.z = fmaf(cA, eA3.z, fmaf(cB, eB3.z, acc3.z));
        acc3.w = fmaf(cA, eA3.w, fmaf(cB, eB3.w, acc3.w));
    }

    // ---- block combine (reuse s_part as float4 buffer) ----
    __syncthreads();   // s_part reads (phase 1.5) long done; safe to overwrite
    float4* sacc = reinterpret_cast<float4*>(&s_part[0][0][0]);
    sacc[w * 128 + 0*32 + lane] = acc0;
    sacc[w * 128 + 1*32 + lane] = acc1;
    sacc[w * 128 + 2*32 + lane] = acc2;
    sacc[w * 128 + 3*32 + lane] = acc3;
    __syncthreads();

    if (tid < 128) {
        float4 v = sacc[tid];
#pragma unroll
        for (int p = 1; p < 8; p++) {
            float4 u = sacc[p * 128 + tid];
            v.x += u.x; v.y += u.y; v.z += u.z; v.w += u.w;
        }
        reinterpret_cast<float4*>(g_pacc)[(b * NS + sp) * 128 + tid] = v;
    }

    // ---- last block per batch finalizes ----
    __threadfence();
    __syncthreads();
    if (tid == 0) {
        int v = atomicAdd(&g_done[b], 1);
        s_last = (v == NS - 1);
    }
    __syncthreads();
    if (!s_last) return;
    __threadfence();

    if (tid == 0) {
        float Z = 0.f;
#pragma unroll
        for (int p = 0; p < NS; p++) Z += __ldcg(&g_pz[b * NS + p]);
        s_invZ = 1.f / Z;
    }
    __syncthreads();
    const float invZ = s_invZ;

    float2 s2 = make_float2(0.f, 0.f);
    const float2* pacc2 = reinterpret_cast<const float2*>(g_pacc);
#pragma unroll
    for (int p = 0; p < NS; p++) {
        float2 v = __ldcg(&pacc2[(b * NS + p) * 256 + tid]);
        s2.x += v.x; s2.y += v.y;
    }
    float2 o2; o2.x = s2.x * invZ; o2.y = s2.y * invZ;
    reinterpret_cast<float2*>(out)[b * 256 + tid] = o2;

    for (int s = tid; s < S_LEN; s += 256)
        out[B_SZ * D_SZ + b * S_LEN + s] = __ldcg(&g_c[b * S_LEN + s]) * invZ;
}

// ---------------- launch ----------------
extern "C" void kernel_launch(void* const* d_in, const int* in_sizes, int n_in,
                              void* d_out, int out_size) {
    const float* enc   = (const float*)d_in[0];
    const float* state = (const float*)d_in[1];
    const float* prev  = (const float*)d_in[2];
    const float* W     = (const float*)d_in[3];
    const float* batt  = (const float*)d_in[4];
    const float* cw    = (const float*)d_in[5];
    const float* cb    = (const float*)d_in[6];
    float* out = (float*)d_out;

    k_gemm<<<dim3(64, KSPL), 256>>>(state, W);
    k_main<<<dim3(B_SZ, NS), 256>>>(enc, batt, prev, cw, cb, out);
}

// round 10
// speedup vs baseline: 1.0177x; 1.0177x over previous
#include <cuda_runtime.h>
#include <cstdint>
#include <math.h>

#define S_LEN 2048
#define B_SZ  32
#define D_SZ  512
#define KCONV 147
#define PADC  73
#define NSP   64                 // s-splits
#define ROWS_PB 32               // rows per block (64 KB in smem)
#define KSPL  4                  // gemm k-splits

// ---------------- scratch ----------------
__device__ float g_attp[KSPL][B_SZ * D_SZ];  // GEMM k-split partials
__device__ float g_c  [B_SZ * S_LEN];        // adj * exp(w)
__device__ float g_pz [B_SZ * NSP];          // per-split sum of c
__device__ float g_pacc[B_SZ * NSP * D_SZ];  // per-split weighted sums (4 MB)
__device__ int   g_done[B_SZ];               // per-batch arrival counters

__device__ __forceinline__ void cp16(unsigned int s, const void* g) {
    asm volatile("cp.async.cg.shared.global [%0], [%1], 16;\n" :: "r"(s), "l"(g) : "memory");
}
__device__ __forceinline__ void cp_commit() {
    asm volatile("cp.async.commit_group;\n" ::: "memory");
}
template <int N>
__device__ __forceinline__ void cp_wait() {
    asm volatile("cp.async.wait_group %0;\n" :: "n"(N) : "memory");
}

// ---------------- kernel 1: attended = state @ W^T (k-split x4) ----------
__global__ __launch_bounds__(256) void k_gemm(const float* __restrict__ state,
                                              const float* __restrict__ W) {
    __shared__ float st[128][33];
    __shared__ float ws[8][128];
    const int tid  = threadIdx.x;
    const int lane = tid & 31;      // batch
    const int wid  = tid >> 5;      // one of 8 d's
    const int gx   = blockIdx.x, gy = blockIdx.y;
    const int k0   = gy * 128;
    const int d    = gx * 8 + wid;

    if (gx == 0 && gy == 0 && tid < B_SZ) g_done[tid] = 0;

    for (int i = tid; i < 32 * 128; i += 256) {
        int b = i >> 7, kk = i & 127;
        st[kk][b] = state[b * D_SZ + k0 + kk];
    }
    for (int i = tid; i < 8 * 128; i += 256) {
        int dd = i >> 7, kk = i & 127;
        ws[dd][kk] = W[(gx * 8 + dd) * D_SZ + k0 + kk];
    }
    __syncthreads();

    float a0 = 0.f, a1 = 0.f, a2 = 0.f, a3 = 0.f;
#pragma unroll 8
    for (int kk = 0; kk < 128; kk += 4) {
        a0 = fmaf(st[kk + 0][lane], ws[wid][kk + 0], a0);
        a1 = fmaf(st[kk + 1][lane], ws[wid][kk + 1], a1);
        a2 = fmaf(st[kk + 2][lane], ws[wid][kk + 2], a2);
        a3 = fmaf(st[kk + 3][lane], ws[wid][kk + 3], a3);
    }
    g_attp[gy][lane * D_SZ + d] = (a0 + a1) + (a2 + a3);
}

// ---------------- kernel 2: smem-resident two-phase main pass -------------
// grid (B_SZ, NSP); 256 threads = 8 warps; 2 blocks/SM (78 KB smem).
// enc is read from DRAM exactly once; phase 2 re-reads from smem.
__global__ __launch_bounds__(256, 2) void k_main(const float* __restrict__ enc,
                                                 const float* __restrict__ b_att,
                                                 const float* __restrict__ prev,
                                                 const float* __restrict__ cw,
                                                 const float* __restrict__ cb,
                                                 float* __restrict__ out) {
    extern __shared__ float s_rows[];            // [32][512] = 64 KB
    __shared__ float4 s_ns[128];
    __shared__ __align__(16) float s_part[2][ROWS_PB][36];
    __shared__ float  s_spc[ROWS_PB + 2 * PADC];
    __shared__ float  s_cw[KCONV];
    __shared__ float  s_adj[ROWS_PB];
    __shared__ float  s_c[ROWS_PB];
    __shared__ float  s_invZ;
    __shared__ int    s_last;

    const int b   = blockIdx.x;
    const int sp  = blockIdx.y;
    const int tid = threadIdx.x, lane = tid & 31, w = tid >> 5;
    const int s0  = sp * ROWS_PB;
    const char* gbase = (const char*)enc;

    const unsigned int sm0 = (unsigned int)__cvta_generic_to_shared(s_rows);

    // ---- cp.async: rows 0-15 (group 1), rows 16-31 (group 0) ----
#pragma unroll
    for (int i = 0; i < 8; i++) {
        int idx = tid + i * 256;                 // float4 index
        int row = idx >> 7, j = idx & 127;
        cp16(sm0 + idx * 16,
             gbase + ((size_t)(s0 + row) * B_SZ + b) * 2048 + j * 16);
    }
    cp_commit();
#pragma unroll
    for (int i = 8; i < 16; i++) {
        int idx = tid + i * 256;
        int row = idx >> 7, j = idx & 127;
        cp16(sm0 + idx * 16,
             gbase + ((size_t)(s0 + row) * B_SZ + b) * 2048 + j * 16);
    }
    cp_commit();

    // ---- stage conv inputs (overlaps async loads) ----
    if (tid < KCONV) s_cw[tid] = cw[tid];
    for (int i = tid; i < ROWS_PB + 2 * PADC; i += 256) {
        int s = s0 + i - PADC;
        s_spc[i] = (s >= 0 && s < S_LEN) ? prev[b * S_LEN + s] : 0.f;
    }

    // ---- warp 0: normalized attended state into s_ns ----
    if (w == 0) {
        const float4* ba4 = reinterpret_cast<const float4*>(b_att);
        float4 a0, a1, a2, a3, t;
#define LD_AT(q, dst) \
        dst = ba4[(q) * 32 + lane]; \
        _Pragma("unroll") \
        for (int p_ = 0; p_ < KSPL; p_++) { \
            t = reinterpret_cast<const float4*>(g_attp[p_])[b * 128 + (q) * 32 + lane]; \
            dst.x += t.x; dst.y += t.y; dst.z += t.z; dst.w += t.w; \
        }
        LD_AT(0, a0) LD_AT(1, a1) LD_AT(2, a2) LD_AT(3, a3)
#undef LD_AT
        float ss = a0.x*a0.x + a0.y*a0.y + a0.z*a0.z + a0.w*a0.w
                 + a1.x*a1.x + a1.y*a1.y + a1.z*a1.z + a1.w*a1.w
                 + a2.x*a2.x + a2.y*a2.y + a2.z*a2.z + a2.w*a2.w
                 + a3.x*a3.x + a3.y*a3.y + a3.z*a3.z + a3.w*a3.w;
#pragma unroll
        for (int o = 16; o; o >>= 1) ss += __shfl_xor_sync(0xffffffffu, ss, o);
        float inv = (ss > 0.f) ? rsqrtf(ss) : 1e10f;
        a0.x*=inv; a0.y*=inv; a0.z*=inv; a0.w*=inv;
        a1.x*=inv; a1.y*=inv; a1.z*=inv; a1.w*=inv;
        a2.x*=inv; a2.y*=inv; a2.z*=inv; a2.w*=inv;
        a3.x*=inv; a3.y*=inv; a3.z*=inv; a3.w*=inv;
        s_ns[0*32 + lane] = a0;
        s_ns[1*32 + lane] = a1;
        s_ns[2*32 + lane] = a2;
        s_ns[3*32 + lane] = a3;
    }
    __syncthreads();   // s_spc / s_cw / s_ns staged

    // ---- conv: 8 threads per output row ----
    {
        const int o_ = tid >> 3, q = tid & 7;
        const int j0 = q * 19, cnt = (q < 7) ? 19 : (KCONV - 7 * 19);  // 19/14
        float a = 0.f, a2 = 0.f;
        for (int j = 0; j < cnt - 1; j += 2) {
            a  = fmaf(s_spc[o_ + j0 + j],     s_cw[j0 + j],     a);
            a2 = fmaf(s_spc[o_ + j0 + j + 1], s_cw[j0 + j + 1], a2);
        }
        if (cnt & 1) a = fmaf(s_spc[o_ + j0 + cnt - 1], s_cw[j0 + cnt - 1], a);
        float v = a + a2;
        v += __shfl_xor_sync(0xffffffffu, v, 1);
        v += __shfl_xor_sync(0xffffffffu, v, 2);
        v += __shfl_xor_sync(0xffffffffu, v, 4);
        if (q == 0) s_adj[o_] = fmaxf(v + __ldg(cb), 0.f);
    }

    // ns into registers
    float4 n0 = s_ns[0*32 + lane], n1 = s_ns[1*32 + lane],
           n2 = s_ns[2*32 + lane], n3 = s_ns[3*32 + lane];

    // ---- phase 1: per-lane partials for 2 rows/warp per group ----
#define DO_PAIR(rA)                                                          \
    {                                                                        \
        const float4* pA = reinterpret_cast<const float4*>(s_rows) + (rA) * 128; \
        const float4* pB = pA + 128;                                         \
        float4 eA0 = pA[lane], eA1 = pA[32+lane], eA2 = pA[64+lane], eA3 = pA[96+lane]; \
        float4 eB0 = pB[lane], eB1 = pB[32+lane], eB2 = pB[64+lane], eB3 = pB[96+lane]; \
        float dA = eA0.x*n0.x + eA0.y*n0.y + eA0.z*n0.z + eA0.w*n0.w         \
                 + eA1.x*n1.x + eA1.y*n1.y + eA1.z*n1.z + eA1.w*n1.w         \
                 + eA2.x*n2.x + eA2.y*n2.y + eA2.z*n2.z + eA2.w*n2.w         \
                 + eA3.x*n3.x + eA3.y*n3.y + eA3.z*n3.z + eA3.w*n3.w;        \
        float sA = eA0.x*eA0.x + eA0.y*eA0.y + eA0.z*eA0.z + eA0.w*eA0.w     \
                 + eA1.x*eA1.x + eA1.y*eA1.y + eA1.z*eA1.z + eA1.w*eA1.w     \
                 + eA2.x*eA2.x + eA2.y*eA2.y + eA2.z*eA2.z + eA2.w*eA2.w     \
                 + eA3.x*eA3.x + eA3.y*eA3.y + eA3.z*eA3.z + eA3.w*eA3.w;    \
        float dB = eB0.x*n0.x + eB0.y*n0.y + eB0.z*n0.z + eB0.w*n0.w         \
                 + eB1.x*n1.x + eB1.y*n1.y + eB1.z*n1.z + eB1.w*n1.w         \
                 + eB2.x*n2.x + eB2.y*n2.y + eB2.z*n2.z + eB2.w*n2.w         \
                 + eB3.x*n3.x + eB3.y*n3.y + eB3.z*n3.z + eB3.w*n3.w;        \
        float sB = eB0.x*eB0.x + eB0.y*eB0.y + eB0.z*eB0.z + eB0.w*eB0.w     \
                 + eB1.x*eB1.x + eB1.y*eB1.y + eB1.z*eB1.z + eB1.w*eB1.w     \
                 + eB2.x*eB2.x + eB2.y*eB2.y + eB2.z*eB2.z + eB2.w*eB2.w     \
                 + eB3.x*eB3.x + eB3.y*eB3.y + eB3.z*eB3.z + eB3.w*eB3.w;    \
        s_part[0][(rA)][lane]     = dA;                                      \
        s_part[1][(rA)][lane]     = sA;                                      \
        s_part[0][(rA) + 1][lane] = dB;                                      \
        s_part[1][(rA) + 1][lane] = sB;                                      \
    }

    cp_wait<1>();          // rows 0-15 landed
    __syncthreads();       // cross-thread visibility
    DO_PAIR(2 * w)
    cp_wait<0>();          // rows 16-31 landed
    __syncthreads();
    DO_PAIR(2 * w + 16)
    __syncthreads();       // partials + s_adj visible
#undef DO_PAIR

    // ---- phase 1.5: octet-reduce partials -> c per row ----
    {
        const int row = tid >> 3, q = tid & 7;
        float4 v = *reinterpret_cast<const float4*>(&s_part[0][row][q * 4]);
        float4 u = *reinterpret_cast<const float4*>(&s_part[1][row][q * 4]);
        float dot = (v.x + v.y) + (v.z + v.w);
        float ss  = (u.x + u.y) + (u.z + u.w);
        dot += __shfl_xor_sync(0xffffffffu, dot, 1);
        ss  += __shfl_xor_sync(0xffffffffu, ss, 1);
        dot += __shfl_xor_sync(0xffffffffu, dot, 2);
        ss  += __shfl_xor_sync(0xffffffffu, ss, 2);
        dot += __shfl_xor_sync(0xffffffffu, dot, 4);
        ss  += __shfl_xor_sync(0xffffffffu, ss, 4);
        if (q == 0) {
            float wt = dot * ((ss > 0.f) ? rsqrtf(ss) : 1e10f);  // |wt| <= 1
            float c = s_adj[row] * __expf(wt);
            s_c[row] = c;
            g_c[b * S_LEN + s0 + row] = c;
        }
    }
    __syncthreads();

    // ---- warp 0: csum -> g_pz (others proceed into phase 2) ----
    if (tid < 32) {
        float z = s_c[lane];
#pragma unroll
        for (int o = 16; o; o >>= 1) z += __shfl_xor_sync(0xffffffffu, z, o);
        if (lane == 0) g_pz[b * NSP + sp] = z;
    }

    // ---- phase 2: weighted accumulation from smem (2 floats/thread) ----
    {
        float2 acc = make_float2(0.f, 0.f);
#pragma unroll
        for (int r = 0; r < ROWS_PB; r += 4) {
            float4 c4 = *reinterpret_cast<const float4*>(&s_c[r]);
            float2 e;
            e = *reinterpret_cast<const float2*>(&s_rows[(r + 0) * 512 + tid * 2]);
            acc.x = fmaf(c4.x, e.x, acc.x); acc.y = fmaf(c4.x, e.y, acc.y);
            e = *reinterpret_cast<const float2*>(&s_rows[(r + 1) * 512 + tid * 2]);
            acc.x = fmaf(c4.y, e.x, acc.x); acc.y = fmaf(c4.y, e.y, acc.y);
            e = *reinterpret_cast<const float2*>(&s_rows[(r + 2) * 512 + tid * 2]);
            acc.x = fmaf(c4.z, e.x, acc.x); acc.y = fmaf(c4.z, e.y, acc.y);
            e = *reinterpret_cast<const float2*>(&s_rows[(r + 3) * 512 + tid * 2]);
            acc.x = fmaf(c4.w, e.x, acc.x); acc.y = fmaf(c4.w, e.y, acc.y);
        }
        reinterpret_cast<float2*>(g_pacc)[(b * NSP + sp) * 256 + tid] = acc;
    }

    // ---- last block per batch finalizes ----
    __threadfence();
    __syncthreads();
    if (tid == 0) {
        int v = atomicAdd(&g_done[b], 1);
        s_last = (v == NSP - 1);
    }
    __syncthreads();
    if (!s_last) return;
    __threadfence();

    if (tid == 0) {
        float Z = 0.f;
#pragma unroll
        for (int p = 0; p < NSP; p++) Z += __ldcg(&g_pz[b * NSP + p]);
        s_invZ = 1.f / Z;
    }
    __syncthreads();
    const float invZ = s_invZ;

    float2 s2 = make_float2(0.f, 0.f);
    const float2* pacc2 = reinterpret_cast<const float2*>(g_pacc);
#pragma unroll 8
    for (int p = 0; p < NSP; p++) {
        float2 v = __ldcg(&pacc2[(b * NSP + p) * 256 + tid]);
        s2.x += v.x; s2.y += v.y;
    }
    float2 o2; o2.x = s2.x * invZ; o2.y = s2.y * invZ;
    reinterpret_cast<float2*>(out)[b * 256 + tid] = o2;

    for (int s = tid; s < S_LEN; s += 256)
        out[B_SZ * D_SZ + b * S_LEN + s] = __ldcg(&g_c[b * S_LEN + s]) * invZ;
}

// ---------------- launch ----------------
extern "C" void kernel_launch(void* const* d_in, const int* in_sizes, int n_in,
                              void* d_out, int out_size) {
    const float* enc   = (const float*)d_in[0];
    const float* state = (const float*)d_in[1];
    const float* prev  = (const float*)d_in[2];
    const float* W     = (const float*)d_in[3];
    const float* batt  = (const float*)d_in[4];
    const float* cw    = (const float*)d_in[5];
    const float* cb    = (const float*)d_in[6];
    float* out = (float*)d_out;

    const int rows_bytes = ROWS_PB * D_SZ * sizeof(float);   // 65536
    cudaFuncSetAttribute(k_main, cudaFuncAttributeMaxDynamicSharedMemorySize,
                         rows_bytes);

    k_gemm<<<dim3(64, KSPL), 256>>>(state, W);
    k_main<<<dim3(B_SZ, NSP), 256, rows_bytes>>>(enc, batt, prev, cw, cb, out);
}

// round 11
// speedup vs baseline: 1.4376x; 1.4126x over previous
#include <cuda_runtime.h>
#include <cstdint>
#include <math.h>

#define S_LEN 2048
#define B_SZ  32
#define D_SZ  512
#define KCONV 147
#define PADC  73
#define NS    32                 // s-splits
#define ROWS_PB 64               // rows per block
#define ROWS_PW 8                // rows per warp (4 groups of 2)
#define KSPL  4                  // gemm k-splits

// ---------------- scratch ----------------
__device__ float g_attp[KSPL][B_SZ * D_SZ];  // GEMM k-split partials
__device__ float g_c  [B_SZ * S_LEN];        // adj * exp(w)
__device__ float g_pz [B_SZ * NS];           // per-split sum of c
__device__ float g_pacc[B_SZ * NS * D_SZ];   // per-split weighted sums
__device__ int   g_done[B_SZ];               // per-batch arrival counters

__device__ __forceinline__ void cp16(unsigned int s, const void* g) {
    asm volatile("cp.async.cg.shared.global [%0], [%1], 16;\n" :: "r"(s), "l"(g) : "memory");
}
__device__ __forceinline__ void cp_commit() {
    asm volatile("cp.async.commit_group;\n" ::: "memory");
}
template <int N>
__device__ __forceinline__ void cp_wait() {
    asm volatile("cp.async.wait_group %0;\n" :: "n"(N) : "memory");
}

// ---------------- kernel 1: attended = state @ W^T (k-split x4) ----------
__global__ __launch_bounds__(256) void k_gemm(const float* __restrict__ state,
                                              const float* __restrict__ W) {
    __shared__ float st[128][33];
    __shared__ float ws[8][128];
    const int tid  = threadIdx.x;
    const int lane = tid & 31;      // batch
    const int wid  = tid >> 5;      // one of 8 d's
    const int gx   = blockIdx.x, gy = blockIdx.y;
    const int k0   = gy * 128;
    const int d    = gx * 8 + wid;

    if (gx == 0 && gy == 0 && tid < B_SZ) g_done[tid] = 0;

    for (int i = tid; i < 32 * 128; i += 256) {
        int b = i >> 7, kk = i & 127;
        st[kk][b] = state[b * D_SZ + k0 + kk];
    }
    for (int i = tid; i < 8 * 128; i += 256) {
        int dd = i >> 7, kk = i & 127;
        ws[dd][kk] = W[(gx * 8 + dd) * D_SZ + k0 + kk];
    }
    __syncthreads();

    float a0 = 0.f, a1 = 0.f, a2 = 0.f, a3 = 0.f;
#pragma unroll 8
    for (int kk = 0; kk < 128; kk += 4) {
        a0 = fmaf(st[kk + 0][lane], ws[wid][kk + 0], a0);
        a1 = fmaf(st[kk + 1][lane], ws[wid][kk + 1], a1);
        a2 = fmaf(st[kk + 2][lane], ws[wid][kk + 2], a2);
        a3 = fmaf(st[kk + 3][lane], ws[wid][kk + 3], a3);
    }
    g_attp[gy][lane * D_SZ + d] = (a0 + a1) + (a2 + a3);
}

// ---------------- kernel 2: paired-row cp.async main pass ------------------
// grid (B_SZ, NS); 256 threads = 8 warps; 3 blocks/SM (regs<=85, 68KB smem).
// Warp processes 2 rows per iteration; one shared butterfly reduces both.
__global__ __launch_bounds__(256, 3) void k_main(const float* __restrict__ enc,
                                                 const float* __restrict__ b_att,
                                                 const float* __restrict__ prev,
                                                 const float* __restrict__ cw,
                                                 const float* __restrict__ cb,
                                                 float* __restrict__ out) {
    extern __shared__ float4 s_ring[];              // [8 warps][2 slots][2 rows][128] = 64 KB
    __shared__ float4 s_ns[128];
    __shared__ float  s_spc[ROWS_PB + 2 * PADC];
    __shared__ float  s_cw[KCONV];
    __shared__ float  s_scs[8];
    __shared__ float  s_invZ;
    __shared__ int    s_last;

    const int b   = blockIdx.x;
    const int sp  = blockIdx.y;
    const int tid = threadIdx.x, lane = tid & 31, w = tid >> 5;

    const int sbase = sp * ROWS_PB + w * ROWS_PW;
    const char* gbase = (const char*)enc;

    const unsigned int ring0 =
        (unsigned int)__cvta_generic_to_shared(s_ring + (size_t)w * 2 * 256);

    // ---- prologue: groups 0,1 (rows 0..3) into slots 0,1 ----
#pragma unroll
    for (int g = 0; g < 2; g++) {
#pragma unroll
        for (int r = 0; r < 2; r++) {
            const char* gp = gbase + ((size_t)(sbase + 2*g + r) * B_SZ + b) * 2048;
            unsigned int sa = ring0 + g * 4096 + r * 2048;
#pragma unroll
            for (int k = 0; k < 4; k++)
                cp16(sa + (k * 32 + lane) * 16, gp + (k * 32 + lane) * 16);
        }
        cp_commit();
    }

    // ---- stage conv inputs (overlaps async loads) ----
    if (tid < KCONV) s_cw[tid] = cw[tid];
    {
        const int c0 = sp * ROWS_PB;
        for (int i = tid; i < ROWS_PB + 2 * PADC; i += 256) {
            int s = c0 + i - PADC;
            s_spc[i] = (s >= 0 && s < S_LEN) ? prev[b * S_LEN + s] : 0.f;
        }
    }

    // ---- warp 0: normalized attended state into s_ns ----
    if (w == 0) {
        const float4* ba4 = reinterpret_cast<const float4*>(b_att);
        float4 a0, a1, a2, a3, t;
#define LD_AT(q, dst) \
        dst = ba4[(q) * 32 + lane]; \
        _Pragma("unroll") \
        for (int p_ = 0; p_ < KSPL; p_++) { \
            t = reinterpret_cast<const float4*>(g_attp[p_])[b * 128 + (q) * 32 + lane]; \
            dst.x += t.x; dst.y += t.y; dst.z += t.z; dst.w += t.w; \
        }
        LD_AT(0, a0) LD_AT(1, a1) LD_AT(2, a2) LD_AT(3, a3)
#undef LD_AT
        float ss = a0.x*a0.x + a0.y*a0.y + a0.z*a0.z + a0.w*a0.w
                 + a1.x*a1.x + a1.y*a1.y + a1.z*a1.z + a1.w*a1.w
                 + a2.x*a2.x + a2.y*a2.y + a2.z*a2.z + a2.w*a2.w
                 + a3.x*a3.x + a3.y*a3.y + a3.z*a3.z + a3.w*a3.w;
#pragma unroll
        for (int o = 16; o; o >>= 1) ss += __shfl_xor_sync(0xffffffffu, ss, o);
        float inv = (ss > 0.f) ? rsqrtf(ss) : 1e10f;
        a0.x*=inv; a0.y*=inv; a0.z*=inv; a0.w*=inv;
        a1.x*=inv; a1.y*=inv; a1.z*=inv; a1.w*=inv;
        a2.x*=inv; a2.y*=inv; a2.z*=inv; a2.w*=inv;
        a3.x*=inv; a3.y*=inv; a3.z*=inv; a3.w*=inv;
        s_ns[0*32 + lane] = a0;
        s_ns[1*32 + lane] = a1;
        s_ns[2*32 + lane] = a2;
        s_ns[3*32 + lane] = a3;
    }
    __syncthreads();

    // ---- conv: quad per output row (warp owns its 8 rows' adj in vfull) ----
    float vfull;
    {
        const int o_ = tid >> 2, q = tid & 3;
        const int j0 = q * 37, cnt = (q < 3) ? 37 : 36;
        float a = 0.f, a2 = 0.f;
        for (int j = 0; j < cnt - 1; j += 2) {
            a  = fmaf(s_spc[o_ + j0 + j],     s_cw[j0 + j],     a);
            a2 = fmaf(s_spc[o_ + j0 + j + 1], s_cw[j0 + j + 1], a2);
        }
        if (cnt & 1) a = fmaf(s_spc[o_ + j0 + cnt - 1], s_cw[j0 + cnt - 1], a);
        vfull = a + a2;
        vfull += __shfl_xor_sync(0xffffffffu, vfull, 1);
        vfull += __shfl_xor_sync(0xffffffffu, vfull, 2);
    }
    const float cb0 = __ldg(cb);

    // ns into registers (loaded once, reused every row)
    float4 n0 = s_ns[0*32 + lane], n1 = s_ns[1*32 + lane],
           n2 = s_ns[2*32 + lane], n3 = s_ns[3*32 + lane];

    // ---- main loop: 4 groups of 2 rows ----
    float4 acc0 = make_float4(0,0,0,0), acc1 = acc0, acc2 = acc0, acc3 = acc0;
    float csum = 0.f;
    const int par = lane & 1;

#pragma unroll
    for (int g = 0; g < 4; g++) {
        cp_wait<1>();
        __syncwarp();

        const float4* pA = s_ring + ((size_t)w * 2 + (g & 1)) * 256;
        const float4* pB = pA + 128;
        float4 eA0 = pA[lane], eA1 = pA[32+lane], eA2 = pA[64+lane], eA3 = pA[96+lane];
        float4 eB0 = pB[lane], eB1 = pB[32+lane], eB2 = pB[64+lane], eB3 = pB[96+lane];

        // refill this slot with group g+2
        if (g + 2 < 4) {
#pragma unroll
            for (int r = 0; r < 2; r++) {
                const char* gp = gbase + ((size_t)(sbase + 2*(g+2) + r) * B_SZ + b) * 2048;
                unsigned int sa = ring0 + (g & 1) * 4096 + r * 2048;
#pragma unroll
                for (int k = 0; k < 4; k++)
                    cp16(sa + (k * 32 + lane) * 16, gp + (k * 32 + lane) * 16);
            }
        }
        cp_commit();    // lockstep group count

        float dA = eA0.x*n0.x + eA0.y*n0.y + eA0.z*n0.z + eA0.w*n0.w
                 + eA1.x*n1.x + eA1.y*n1.y + eA1.z*n1.z + eA1.w*n1.w
                 + eA2.x*n2.x + eA2.y*n2.y + eA2.z*n2.z + eA2.w*n2.w
                 + eA3.x*n3.x + eA3.y*n3.y + eA3.z*n3.z + eA3.w*n3.w;
        float sA = eA0.x*eA0.x + eA0.y*eA0.y + eA0.z*eA0.z + eA0.w*eA0.w
                 + eA1.x*eA1.x + eA1.y*eA1.y + eA1.z*eA1.z + eA1.w*eA1.w
                 + eA2.x*eA2.x + eA2.y*eA2.y + eA2.z*eA2.z + eA2.w*eA2.w
                 + eA3.x*eA3.x + eA3.y*eA3.y + eA3.z*eA3.z + eA3.w*eA3.w;
        float dB = eB0.x*n0.x + eB0.y*n0.y + eB0.z*n0.z + eB0.w*n0.w
                 + eB1.x*n1.x + eB1.y*n1.y + eB1.z*n1.z + eB1.w*n1.w
                 + eB2.x*n2.x + eB2.y*n2.y + eB2.z*n2.z + eB2.w*n2.w
                 + eB3.x*n3.x + eB3.y*n3.y + eB3.z*n3.z + eB3.w*n3.w;
        float sB = eB0.x*eB0.x + eB0.y*eB0.y + eB0.z*eB0.z + eB0.w*eB0.w
                 + eB1.x*eB1.x + eB1.y*eB1.y + eB1.z*eB1.z + eB1.w*eB1.w
                 + eB2.x*eB2.x + eB2.y*eB2.y + eB2.z*eB2.z + eB2.w*eB2.w
                 + eB3.x*eB3.x + eB3.y*eB3.y + eB3.z*eB3.z + eB3.w*eB3.w;

        // pair-merge: even lanes carry row A, odd lanes carry row B
        float dM = (par ? dB : dA) + __shfl_xor_sync(0xffffffffu, par ? dA : dB, 1);
        float sM = (par ? sB : sA) + __shfl_xor_sync(0xffffffffu, par ? sA : sB, 1);
#pragma unroll
        for (int o = 2; o <= 16; o <<= 1) {
            dM += __shfl_xor_sync(0xffffffffu, dM, o);
            sM += __shfl_xor_sync(0xffffffffu, sM, o);
        }
        // lane has full dot/ss of row `par`
        float wt = dM * ((sM > 0.f) ? rsqrtf(sM) : 1e10f);     // |wt| <= 1
        float adjr = fmaxf(__shfl_sync(0xffffffffu, vfull, 8*g + 4*par) + cb0, 0.f);
        float c_own = adjr * __expf(wt);
        if (lane < 2) g_c[b * S_LEN + sbase + 2*g + lane] = c_own;
        float c_oth = __shfl_xor_sync(0xffffffffu, c_own, 1);
        float cA = par ? c_oth : c_own;
        float cB = par ? c_own : c_oth;
        csum += cA + cB;

        acc0.x = fmaf(cA, eA0.x, fmaf(cB, eB0.x, acc0.x));
        acc0.y = fmaf(cA, eA0.y, fmaf(cB, eB0.y, acc0.y));
        acc0.z = fmaf(cA, eA0.z, fmaf(cB, eB0.z, acc0.z));
        acc0.w = fmaf(cA, eA0.w, fmaf(cB, eB0.w, acc0.w));
        acc1.x = fmaf(cA, eA1.x, fmaf(cB, eB1.x, acc1.x));
        acc1.y = fmaf(cA, eA1.y, fmaf(cB, eB1.y, acc1.y));
        acc1.z = fmaf(cA, eA1.z, fmaf(cB, eB1.z, acc1.z));
        acc1.w = fmaf(cA, eA1.w, fmaf(cB, eB1.w, acc1.w));
        acc2.x = fmaf(cA, eA2.x, fmaf(cB, eB2.x, acc2.x));
        acc2.y = fmaf(cA, eA2.y, fmaf(cB, eB2.y, acc2.y));
        acc2.z = fmaf(cA, eA2.z, fmaf(cB, eB2.z, acc2.z));
        acc2.w = fmaf(cA, eA2.w, fmaf(cB, eB2.w, acc2.w));
        acc3.x = fmaf(cA, eA3.x, fmaf(cB, eB3.x, acc3.x));
        acc3.y = fmaf(cA, eA3.y, fmaf(cB, eB3.y, acc3.y));
        acc3.z = fmaf(cA, eA3.z, fmaf(cB, eB3.z, acc3.z));
        acc3.w = fmaf(cA, eA3.w, fmaf(cB, eB3.w, acc3.w));
    }

    // ---- block combine (reuse the ring) ----
    __syncthreads();
    float4* sacc = s_ring;
    sacc[w * 128 + 0*32 + lane] = acc0;
    sacc[w * 128 + 1*32 + lane] = acc1;
    sacc[w * 128 + 2*32 + lane] = acc2;
    sacc[w * 128 + 3*32 + lane] = acc3;
    if (lane == 0) s_scs[w] = csum;
    __syncthreads();

    if (tid < 128) {
        float4 v = sacc[tid];
#pragma unroll
        for (int p = 1; p < 8; p++) {
            float4 u = sacc[p * 128 + tid];
            v.x += u.x; v.y += u.y; v.z += u.z; v.w += u.w;
        }
        reinterpret_cast<float4*>(g_pacc)[(b * NS + sp) * 128 + tid] = v;
    }
    if (tid == 0) {
        float z = 0.f;
#pragma unroll
        for (int p = 0; p < 8; p++) z += s_scs[p];
        g_pz[b * NS + sp] = z;
    }

    // ---- last block per batch finalizes ----
    __threadfence();
    __syncthreads();
    if (tid == 0) {
        int v = atomicAdd(&g_done[b], 1);
        s_last = (v == NS - 1);
    }
    __syncthreads();
    if (!s_last) return;
    __threadfence();

    if (tid == 0) {
        float Z = 0.f;
#pragma unroll
        for (int p = 0; p < NS; p++) Z += __ldcg(&g_pz[b * NS + p]);
        s_invZ = 1.f / Z;
    }
    __syncthreads();
    const float invZ = s_invZ;

    float2 s2 = make_float2(0.f, 0.f);
    const float2* pacc2 = reinterpret_cast<const float2*>(g_pacc);
#pragma unroll
    for (int p = 0; p < NS; p++) {
        float2 v = __ldcg(&pacc2[(b * NS + p) * 256 + tid]);
        s2.x += v.x; s2.y += v.y;
    }
    float2 o2; o2.x = s2.x * invZ; o2.y = s2.y * invZ;
    reinterpret_cast<float2*>(out)[b * 256 + tid] = o2;

    for (int s = tid; s < S_LEN; s += 256)
        out[B_SZ * D_SZ + b * S_LEN + s] = __ldcg(&g_c[b * S_LEN + s]) * invZ;
}

// ---------------- launch ----------------
extern "C" void kernel_launch(void* const* d_in, const int* in_sizes, int n_in,
                              void* d_out, int out_size) {
    const float* enc   = (const float*)d_in[0];
    const float* state = (const float*)d_in[1];
    const float* prev  = (const float*)d_in[2];
    const float* W     = (const float*)d_in[3];
    const float* batt  = (const float*)d_in[4];
    const float* cw    = (const float*)d_in[5];
    const float* cb    = (const float*)d_in[6];
    float* out = (float*)d_out;

    const int ring_bytes = 8 * 2 * 2 * 2048;   // 65536
    cudaFuncSetAttribute(k_main, cudaFuncAttributeMaxDynamicSharedMemorySize,
                         ring_bytes);

    k_gemm<<<dim3(64, KSPL), 256>>>(state, W);
    k_main<<<dim3(B_SZ, NS), 256, ring_bytes>>>(enc, batt, prev, cw, cb, out);
}